// round 9
// baseline (speedup 1.0000x reference)
#include <cuda_runtime.h>
#include <cuda_bf16.h>

// B=64, H=W=1024, patch=64 -> 16x16 = 256 patches/img, 16384 patches.
// final = mean_b( max_patch( mean_{64x64} |o - t| ) )
//
// Persistent warp-autonomous kernel: grid = 148*3 = 444 blocks x 256 thr,
// 3552 warps. Each WARP owns whole patches (strided), reducing each with
// shuffles only -- no smem, no __syncthreads in the mainloop. Per patch:
// lane = (row parity, float4 col); 4 iterations of 16 front-batched LDG.128.

#define B 64
#define HW 1024
#define P 64
#define NPATCH 16384
#define NBLK 444                       // 148 SMs * 3 CTAs
#define NWARPS (NBLK * 8)              // 3552
#define PATCH_ELEMS (P * P)            // 4096

__device__ unsigned int g_img_max[B];  // zero-init; reset by last warp
__device__ unsigned int g_counter;     // monotone, wrap-safe

__global__ __launch_bounds__(256, 3) void patch_loss_warp_kernel(
    const float* __restrict__ o, const float* __restrict__ t,
    float* __restrict__ out)
{
    const int tid  = threadIdx.x;
    const int lane = tid & 31;
    const int gw   = blockIdx.x * 8 + (tid >> 5);   // global warp id 0..3551

    const float4* __restrict__ o4 = reinterpret_cast<const float4*>(o);
    const float4* __restrict__ t4 = reinterpret_cast<const float4*>(t);

    // lane layout within a patch (16 float4 cols x 64 rows):
    // col = lane & 15 (float4 column), r0 = lane >> 4 (row parity)
    const int col = lane & 15;
    const int r0  = lane >> 4;
    const int loff = r0 * 256 + col;    // f4 offset of lane's first element

    for (int p = gw; p < NPATCH; p += NWARPS) {
        const int img = p >> 8;
        const int ph  = (p >> 4) & 15;
        const int pw  = p & 15;
        // base in float4 units: img*(1<<18) + ph*64*256 + pw*16
        const size_t base = ((size_t)img << 18) + (ph << 14) + (pw << 4);
        const size_t off0 = base + loff;

        float acc0 = 0.0f, acc1 = 0.0f;
#pragma unroll
        for (int i = 0; i < 4; i++) {
            // rows r0 + 2*(8i+j), j=0..7 -> f4 offset off0 + i*4096 + j*512
            float4 av[8], bv[8];
#pragma unroll
            for (int j = 0; j < 8; j++) av[j] = __ldcs(&o4[off0 + i * 4096 + j * 512]);
#pragma unroll
            for (int j = 0; j < 8; j++) bv[j] = __ldcs(&t4[off0 + i * 4096 + j * 512]);
#pragma unroll
            for (int j = 0; j < 8; j += 2) {
                acc0 += fabsf(av[j].x - bv[j].x) + fabsf(av[j].y - bv[j].y)
                      + fabsf(av[j].z - bv[j].z) + fabsf(av[j].w - bv[j].w);
                acc1 += fabsf(av[j+1].x - bv[j+1].x) + fabsf(av[j+1].y - bv[j+1].y)
                      + fabsf(av[j+1].z - bv[j+1].z) + fabsf(av[j+1].w - bv[j+1].w);
            }
        }
        float acc = acc0 + acc1;
        // full-warp sum: patch sum in every lane
#pragma unroll
        for (int s = 16; s > 0; s >>= 1)
            acc += __shfl_xor_sync(0xFFFFFFFFu, acc, s);
        if (lane == 0)
            atomicMax(&g_img_max[img], __float_as_uint(acc)); // >=0: monotone bits
    }

    // completion: last warp does the final 64-max mean
    __threadfence();
    int is_last = 0;
    if (lane == 0) {
        unsigned int old = atomicAdd(&g_counter, 1u);
        is_last = ((old % NWARPS) == (NWARPS - 1));
    }
    is_last = __shfl_sync(0xFFFFFFFFu, is_last, 0);

    if (is_last) {
        __threadfence();
        unsigned int b0 = atomicOr(&g_img_max[lane], 0u);        // atomic read
        unsigned int b1 = atomicOr(&g_img_max[lane + 32], 0u);
        float m = __uint_as_float(b0) + __uint_as_float(b1);
#pragma unroll
        for (int s = 16; s > 0; s >>= 1)
            m += __shfl_xor_sync(0xFFFFFFFFu, m, s);
        if (lane == 0)
            *out = m * (1.0f / (float)PATCH_ELEMS / (float)B);
        __syncwarp();
        g_img_max[lane] = 0u;            // reset for next replay
        g_img_max[lane + 32] = 0u;
    }
}

extern "C" void kernel_launch(void* const* d_in, const int* in_sizes, int n_in,
                              void* d_out, int out_size)
{
    const float* o = (const float*)d_in[0];
    const float* t = (const float*)d_in[1];
    float* out = (float*)d_out;
    patch_loss_warp_kernel<<<NBLK, 256>>>(o, t, out);
}

// round 10
// speedup vs baseline: 1.0092x; 1.0092x over previous
#include <cuda_runtime.h>
#include <cuda_bf16.h>

// B=64, H=W=1024, patch=64 -> 16x16 = 256 patches/img.
// final = mean_b( max_patch( mean_{64x64} |o - t| ) )
//
// Best-measured engine (R6): one block per horizontally-adjacent patch PAIR,
// grid 8192, 256 threads, all 16 LDG.128 per thread front-batched (interleaved
// o/t). Lanes 0-15 hold patch0, 16-31 patch1. Epilogue streamlined: parallel
// funnel reduce + single atomicMax per block.

#define B 64
#define HW 1024
#define P 64
#define NBLOCKS (B * 16 * 8)            // 8192
#define PATCH_ELEMS (P * P)             // 4096

__device__ unsigned int g_img_max[B];   // zero-init; re-zeroed by last block
__device__ unsigned int g_counter;      // monotone, wrap-safe

__global__ __launch_bounds__(256, 3) void patch_loss_pair_kernel(
    const float* __restrict__ o, const float* __restrict__ t,
    float* __restrict__ out)
{
    const int blk  = blockIdx.x;          // 0..8191
    const int img  = blk >> 7;
    const int ph   = (blk >> 3) & 15;
    const int pair = blk & 7;

    const size_t base = (size_t)img * (HW * HW) + (size_t)ph * (P * HW)
                      + (size_t)pair * 128;
    const float4* __restrict__ o4 = reinterpret_cast<const float4*>(o + base);
    const float4* __restrict__ t4 = reinterpret_cast<const float4*>(t + base);

    const int tid = threadIdx.x;
    const int col = tid & 31;             // float4 col within pair (== lane)
    const int rg  = tid >> 5;             // row group 0..7
    const int off0 = rg * 256 + col;      // rows rg + i*8; row stride 256 f4

    // Front-batch all 16 loads, interleaved o/t.
    float4 av[8], bv[8];
#pragma unroll
    for (int i = 0; i < 8; i++) {
        av[i] = __ldcs(&o4[off0 + i * 2048]);
        bv[i] = __ldcs(&t4[off0 + i * 2048]);
    }

    float acc0 = 0.0f, acc1 = 0.0f;
#pragma unroll
    for (int i = 0; i < 8; i += 2) {
        acc0 += fabsf(av[i].x - bv[i].x) + fabsf(av[i].y - bv[i].y)
              + fabsf(av[i].z - bv[i].z) + fabsf(av[i].w - bv[i].w);
        acc1 += fabsf(av[i+1].x - bv[i+1].x) + fabsf(av[i+1].y - bv[i+1].y)
              + fabsf(av[i+1].z - bv[i+1].z) + fabsf(av[i+1].w - bv[i+1].w);
    }
    float acc = acc0 + acc1;

    // Reduce within each 16-lane half (one patch per half).
#pragma unroll
    for (int s = 8; s > 0; s >>= 1)
        acc += __shfl_xor_sync(0xFFFFFFFFu, acc, s);

    // Funnel: 16 partials (8 warps x 2 patches) -> parallel warp-0 reduce.
    __shared__ float parts[16];
    __shared__ bool s_is_last;
    const int lane = tid & 31;
    const int wid = tid >> 5;
    if (lane == 0)  parts[wid] = acc;          // patch0 partial of row-group
    if (lane == 16) parts[wid + 8] = acc;      // patch1 partial
    __syncthreads();

    if (wid == 0) {
        // lanes 0..15 each hold one partial; sum each patch's 8 with shuffles
        float v = (lane < 16) ? parts[lane] : 0.0f;
#pragma unroll
        for (int s = 4; s > 0; s >>= 1)          // reduce within 8-lane groups
            v += __shfl_xor_sync(0xFFFFFFFFu, v, s);
        // lane 0 -> patch0 sum, lane 8 -> patch1 sum
        float v0 = __shfl_sync(0xFFFFFFFFu, v, 0);
        float v1 = __shfl_sync(0xFFFFFFFFu, v, 8);
        if (lane == 0) {
            float vm = fmaxf(v0, v1);
            atomicMax(&g_img_max[img], __float_as_uint(vm)); // >=0: monotone
            __threadfence();
            unsigned int old = atomicAdd(&g_counter, 1u);
            s_is_last = ((old % NBLOCKS) == (NBLOCKS - 1));
        }
    }
    __syncthreads();

    if (s_is_last) {
        __threadfence();
        if (wid == 0) {
            unsigned int b0 = atomicOr(&g_img_max[lane], 0u);
            unsigned int b1 = atomicOr(&g_img_max[lane + 32], 0u);
            float m = __uint_as_float(b0) + __uint_as_float(b1);
#pragma unroll
            for (int s = 16; s > 0; s >>= 1)
                m += __shfl_xor_sync(0xFFFFFFFFu, m, s);
            if (lane == 0)
                *out = m * (1.0f / (float)PATCH_ELEMS / (float)B);
            __syncwarp();
            g_img_max[lane] = 0u;                // reset for next replay
            g_img_max[lane + 32] = 0u;
        }
    }
}

extern "C" void kernel_launch(void* const* d_in, const int* in_sizes, int n_in,
                              void* d_out, int out_size)
{
    const float* o = (const float*)d_in[0];
    const float* t = (const float*)d_in[1];
    float* out = (float*)d_out;
    patch_loss_pair_kernel<<<NBLOCKS, 256>>>(o, t, out);
}

// round 11
// speedup vs baseline: 1.0261x; 1.0167x over previous
#include <cuda_runtime.h>
#include <cuda_bf16.h>

// B=64, H=W=1024, patch=64 -> 16x16 = 256 patches/img.
// final = mean_b( max_patch( mean_{64x64} |o - t| ) )
//
// Empirical optimum (R6, 78.2us): one block per PAIR of horizontally adjacent
// patches, grid = 64*16*8 = 8192, 256 threads. Thread tid owns float4-col
// (tid&31) and row group (tid>>5); 8 o-loads then 8 t-loads, all 16 LDG.128
// front-batched. Lanes 0-15 hold patch0, 16-31 patch1: half-warp shuffle
// yields both patch sums per warp. Fused last-block epilogue.

#define B 64
#define HW 1024
#define P 64
#define NBLOCKS (B * 16 * 8)            // 8192
#define PATCH_ELEMS (P * P)             // 4096

__device__ unsigned int g_img_max[B];   // zero-init; re-zeroed by last block
__device__ unsigned int g_counter;      // monotone, wrap-safe

__global__ __launch_bounds__(256, 3) void patch_loss_pair_kernel(
    const float* __restrict__ o, const float* __restrict__ t,
    float* __restrict__ out)
{
    const int blk  = blockIdx.x;          // 0..8191
    const int img  = blk >> 7;            // /128
    const int ph   = (blk >> 3) & 15;
    const int pair = blk & 7;             // patch-col pair 0..7

    // pair covers cols [pair*128, pair*128+128)
    const size_t base = (size_t)img * (HW * HW) + (size_t)ph * (P * HW)
                      + (size_t)pair * 128;
    const float4* __restrict__ o4 = reinterpret_cast<const float4*>(o + base);
    const float4* __restrict__ t4 = reinterpret_cast<const float4*>(t + base);

    const int tid = threadIdx.x;
    const int col = tid & 31;             // float4 col within pair (== lane)
    const int rg  = tid >> 5;             // row group 0..7

    // rows handled: rg + i*8, i = 0..7; row stride = 256 float4
    const int off0 = rg * 256 + col;

    float4 av[8], bv[8];
#pragma unroll
    for (int i = 0; i < 8; i++) av[i] = __ldcs(&o4[off0 + i * 2048]);
#pragma unroll
    for (int i = 0; i < 8; i++) bv[i] = __ldcs(&t4[off0 + i * 2048]);

    float acc = 0.0f;
#pragma unroll
    for (int i = 0; i < 8; i++) {
        acc += fabsf(av[i].x - bv[i].x) + fabsf(av[i].y - bv[i].y)
             + fabsf(av[i].z - bv[i].z) + fabsf(av[i].w - bv[i].w);
    }

    // Reduce within each 16-lane half (one patch per half).
#pragma unroll
    for (int s = 8; s > 0; s >>= 1)
        acc += __shfl_xor_sync(0xFFFFFFFFu, acc, s);

    __shared__ float warp_sums[2][8];
    __shared__ bool s_is_last;
    const int lane = tid & 31;
    const int wid = tid >> 5;
    if (lane == 0)  warp_sums[0][wid] = acc;   // patch0 partial (rows of rg)
    if (lane == 16) warp_sums[1][wid] = acc;   // patch1 partial
    __syncthreads();

    if (tid == 0) {
        float v0 = 0.f, v1 = 0.f;
#pragma unroll
        for (int w = 0; w < 8; w++) { v0 += warp_sums[0][w]; v1 += warp_sums[1][w]; }
        // sums >= 0: float bits monotone as unsigned
        atomicMax(&g_img_max[img], __float_as_uint(v0));
        atomicMax(&g_img_max[img], __float_as_uint(v1));
        __threadfence();
        unsigned int old = atomicAdd(&g_counter, 1u);
        s_is_last = ((old % NBLOCKS) == (NBLOCKS - 1));
    }
    __syncthreads();

    if (s_is_last) {
        __threadfence();
        __shared__ float red[2];
        if (wid < 2) {
            int i = wid * 32 + lane;                     // 0..63
            unsigned int bits = atomicOr(&g_img_max[i], 0u);
            float m = __uint_as_float(bits);
#pragma unroll
            for (int s = 16; s > 0; s >>= 1)
                m += __shfl_xor_sync(0xFFFFFFFFu, m, s);
            if (lane == 0) red[wid] = m;
        }
        __syncthreads();
        if (tid == 0)
            *out = (red[0] + red[1]) * (1.0f / (float)PATCH_ELEMS / (float)B);
        __syncthreads();
        if (tid < B) g_img_max[tid] = 0u;   // reset for next replay
    }
}

extern "C" void kernel_launch(void* const* d_in, const int* in_sizes, int n_in,
                              void* d_out, int out_size)
{
    const float* o = (const float*)d_in[0];
    const float* t = (const float*)d_in[1];
    float* out = (float*)d_out;
    patch_loss_pair_kernel<<<NBLOCKS, 256>>>(o, t, out);
}

// round 12
// speedup vs baseline: 1.0294x; 1.0033x over previous
#include <cuda_runtime.h>
#include <cuda_bf16.h>

// B=64, H=W=1024, patch=64 -> 16x16 = 256 patches/img.
// final = mean_b( max_patch( mean_{64x64} |o - t| ) )
//
// Empirical optimum (R6, 78.2us best / 78.6us repro): one block per PAIR of
// horizontally adjacent patches, grid = 64*16*8 = 8192, 256 threads. Thread
// tid owns float4-col (tid&31) and row group (tid>>5); 8 o-loads then 8
// t-loads, all 16 LDG.128 front-batched. Lanes 0-15 hold patch0, 16-31
// patch1: half-warp shuffle yields both patch sums per warp. Fused last-block
// epilogue (atomicMax per image + monotone counter), graph-replay safe.
// Measured at ~6.9 TB/s = achievable HBM ceiling for this access pattern.

#define B 64
#define HW 1024
#define P 64
#define NBLOCKS (B * 16 * 8)            // 8192
#define PATCH_ELEMS (P * P)             // 4096

__device__ unsigned int g_img_max[B];   // zero-init; re-zeroed by last block
__device__ unsigned int g_counter;      // monotone, wrap-safe

__global__ __launch_bounds__(256, 3) void patch_loss_pair_kernel(
    const float* __restrict__ o, const float* __restrict__ t,
    float* __restrict__ out)
{
    const int blk  = blockIdx.x;          // 0..8191
    const int img  = blk >> 7;            // /128
    const int ph   = (blk >> 3) & 15;
    const int pair = blk & 7;             // patch-col pair 0..7

    // pair covers cols [pair*128, pair*128+128)
    const size_t base = (size_t)img * (HW * HW) + (size_t)ph * (P * HW)
                      + (size_t)pair * 128;
    const float4* __restrict__ o4 = reinterpret_cast<const float4*>(o + base);
    const float4* __restrict__ t4 = reinterpret_cast<const float4*>(t + base);

    const int tid = threadIdx.x;
    const int col = tid & 31;             // float4 col within pair (== lane)
    const int rg  = tid >> 5;             // row group 0..7

    // rows handled: rg + i*8, i = 0..7; row stride = 256 float4
    const int off0 = rg * 256 + col;

    float4 av[8], bv[8];
#pragma unroll
    for (int i = 0; i < 8; i++) av[i] = __ldcs(&o4[off0 + i * 2048]);
#pragma unroll
    for (int i = 0; i < 8; i++) bv[i] = __ldcs(&t4[off0 + i * 2048]);

    float acc = 0.0f;
#pragma unroll
    for (int i = 0; i < 8; i++) {
        acc += fabsf(av[i].x - bv[i].x) + fabsf(av[i].y - bv[i].y)
             + fabsf(av[i].z - bv[i].z) + fabsf(av[i].w - bv[i].w);
    }

    // Reduce within each 16-lane half (one patch per half).
#pragma unroll
    for (int s = 8; s > 0; s >>= 1)
        acc += __shfl_xor_sync(0xFFFFFFFFu, acc, s);

    __shared__ float warp_sums[2][8];
    __shared__ bool s_is_last;
    const int lane = tid & 31;
    const int wid = tid >> 5;
    if (lane == 0)  warp_sums[0][wid] = acc;   // patch0 partial (rows of rg)
    if (lane == 16) warp_sums[1][wid] = acc;   // patch1 partial
    __syncthreads();

    if (tid == 0) {
        float v0 = 0.f, v1 = 0.f;
#pragma unroll
        for (int w = 0; w < 8; w++) { v0 += warp_sums[0][w]; v1 += warp_sums[1][w]; }
        // sums >= 0: float bits monotone as unsigned
        atomicMax(&g_img_max[img], __float_as_uint(v0));
        atomicMax(&g_img_max[img], __float_as_uint(v1));
        __threadfence();
        unsigned int old = atomicAdd(&g_counter, 1u);
        s_is_last = ((old % NBLOCKS) == (NBLOCKS - 1));
    }
    __syncthreads();

    if (s_is_last) {
        __threadfence();
        __shared__ float red[2];
        if (wid < 2) {
            int i = wid * 32 + lane;                     // 0..63
            unsigned int bits = atomicOr(&g_img_max[i], 0u);
            float m = __uint_as_float(bits);
#pragma unroll
            for (int s = 16; s > 0; s >>= 1)
                m += __shfl_xor_sync(0xFFFFFFFFu, m, s);
            if (lane == 0) red[wid] = m;
        }
        __syncthreads();
        if (tid == 0)
            *out = (red[0] + red[1]) * (1.0f / (float)PATCH_ELEMS / (float)B);
        __syncthreads();
        if (tid < B) g_img_max[tid] = 0u;   // reset for next replay
    }
}

extern "C" void kernel_launch(void* const* d_in, const int* in_sizes, int n_in,
                              void* d_out, int out_size)
{
    const float* o = (const float*)d_in[0];
    const float* t = (const float*)d_in[1];
    float* out = (float*)d_out;
    patch_loss_pair_kernel<<<NBLOCKS, 256>>>(o, t, out);
}